// round 4
// baseline (speedup 1.0000x reference)
#include <cuda_runtime.h>
#include <math.h>

#define N_MAX 100000
#define E_MAX 1600000
#define HID 128
#define EPSBN 1e-5f

// ---------------- scratch (device globals; no allocation) ----------------
__device__ float g_bufA[N_MAX * HID];
__device__ float g_bufB[N_MAX * HID];
__device__ float g_bufC[N_MAX * HID];
__device__ float g_dinv[N_MAX];
__device__ int   g_cnt[N_MAX];
__device__ int   g_rowptr[N_MAX + 1];
__device__ int   g_csr_src[E_MAX];
__device__ float g_csr_w[E_MAX];
__device__ float g_colsum[HID];
__device__ float g_colsq[HID];
__device__ float g_f[N_MAX * 32];

__device__ __forceinline__ float* selbuf(int s) {
    return (s == 0) ? g_bufA : (s == 1) ? g_bufB : g_bufC;
}

// ---------------- CSR build ----------------
__global__ void zero_cnt_kernel(int n) {
    int i = blockIdx.x * blockDim.x + threadIdx.x;
    if (i < n) g_cnt[i] = 0;
}

__global__ void count_kernel(const int* __restrict__ ei, int e) {
    int i = blockIdx.x * blockDim.x + threadIdx.x;
    if (i < e) {
        int dst = ei[e + i];
        atomicAdd(&g_cnt[dst], 1);
    }
}

// single-block exclusive scan over g_cnt -> g_rowptr, plus dinv, then rezero cnt as cursor
__global__ void scan_kernel(int n) {
    __shared__ int sums[1024];
    int tid = threadIdx.x;
    int chunk = (n + 1023) / 1024;
    int start = tid * chunk;
    int end = start + chunk; if (end > n) end = n;
    int s = 0;
    for (int i = start; i < end; i++) s += g_cnt[i];
    sums[tid] = s;
    __syncthreads();
    if (tid == 0) {
        int acc = 0;
        for (int i = 0; i < 1024; i++) { int v = sums[i]; sums[i] = acc; acc += v; }
        g_rowptr[n] = acc;
    }
    __syncthreads();
    int acc = sums[tid];
    for (int i = start; i < end; i++) {
        g_rowptr[i] = acc;
        int c = g_cnt[i];
        acc += c;
        g_dinv[i] = rsqrtf((float)c + 1.0f);  // +1 self-loop
        g_cnt[i] = 0;                          // reset as fill cursor
    }
}

__global__ void fill_kernel(const int* __restrict__ ei, int e) {
    int i = blockIdx.x * blockDim.x + threadIdx.x;
    if (i < e) {
        int src = ei[i];
        int dst = ei[e + i];
        int pos = atomicAdd(&g_cnt[dst], 1);
        int idx = g_rowptr[dst] + pos;
        g_csr_src[idx] = src;
        g_csr_w[idx] = g_dinv[src] * g_dinv[dst];
    }
}

// ---------------- encoder: h = relu(x @ We + be), x[N,2] ----------------
__global__ void encoder_kernel(const float* __restrict__ x, const float* __restrict__ We,
                               const float* __restrict__ be, int out_sel, int n) {
    int i = blockIdx.x;
    int j = threadIdx.x;
    if (i >= n) return;
    float v = x[2 * i] * We[j] + x[2 * i + 1] * We[HID + j] + be[j];
    selbuf(out_sel)[i * HID + j] = fmaxf(v, 0.0f);
}

// ---------------- GEMM: C[N,128] = A[N,128] @ B[128,128] ----------------
// block = 256 threads, tile = 32 rows x 128 cols, 4x4 register micro-tile
__global__ void gemm128_kernel(int a_sel, const float* __restrict__ B, int c_sel, int n) {
    __shared__ float As[32][HID];     // 16 KB
    __shared__ float Bs[64][HID];     // 32 KB
    const float* A = selbuf(a_sel);
    float* C = selbuf(c_sel);

    int tid = threadIdx.x;
    int tx = tid & 31;   // col group: cols 4*tx .. 4*tx+3
    int ty = tid >> 5;   // row group: rows 4*ty .. 4*ty+3
    int row0 = blockIdx.x * 32;

    for (int i = tid; i < 32 * HID; i += 256) {
        int r = i >> 7, c = i & 127;
        As[r][c] = (row0 + r < n) ? A[(row0 + r) * HID + c] : 0.0f;
    }

    float acc[4][4];
#pragma unroll
    for (int i = 0; i < 4; i++)
#pragma unroll
        for (int j = 0; j < 4; j++) acc[i][j] = 0.0f;

    for (int half = 0; half < 2; half++) {
        __syncthreads();
        for (int i = tid; i < 64 * HID; i += 256)
            Bs[i >> 7][i & 127] = B[(half * 64 + (i >> 7)) * HID + (i & 127)];
        __syncthreads();
#pragma unroll
        for (int k = 0; k < 64; k++) {
            float4 b = *(const float4*)&Bs[k][tx * 4];
#pragma unroll
            for (int i = 0; i < 4; i++) {
                float a = As[4 * ty + i][half * 64 + k];
                acc[i][0] += a * b.x;
                acc[i][1] += a * b.y;
                acc[i][2] += a * b.z;
                acc[i][3] += a * b.w;
            }
        }
    }
#pragma unroll
    for (int i = 0; i < 4; i++) {
        int row = row0 + 4 * ty + i;
        if (row < n) {
            float4 v = make_float4(acc[i][0], acc[i][1], acc[i][2], acc[i][3]);
            *(float4*)&C[row * HID + tx * 4] = v;
        }
    }
}

// ---------------- aggregation: out[d] = dinv[d]^2 * t[d] + sum_e w_e * t[src_e] ----------------
__global__ void agg_kernel(int t_sel, int out_sel, int n) {
    int gid = blockIdx.x * blockDim.x + threadIdx.x;
    int node = gid >> 5;
    int lane = gid & 31;
    if (node >= n) return;
    const float4* t = (const float4*)selbuf(t_sel);
    float4* out = (float4*)selbuf(out_sel);

    float di = g_dinv[node];
    float w0 = di * di;
    float4 v = t[node * 32 + lane];
    float4 acc = make_float4(v.x * w0, v.y * w0, v.z * w0, v.w * w0);
    int beg = g_rowptr[node];
    int end = g_rowptr[node + 1];
    for (int e = beg; e < end; e++) {
        int s = g_csr_src[e];
        float w = g_csr_w[e];
        float4 u = t[s * 32 + lane];
        acc.x += w * u.x; acc.y += w * u.y; acc.z += w * u.z; acc.w += w * u.w;
    }
    out[node * 32 + lane] = acc;
}

// ---------------- batchnorm ----------------
__global__ void zero_stats_kernel() {
    int j = threadIdx.x;
    g_colsum[j] = 0.0f;
    g_colsq[j] = 0.0f;
}

__global__ void bnstats_kernel(int v_sel, const float* __restrict__ b, int n) {
    const float* v = selbuf(v_sel);
    int j = threadIdx.x;  // 128
    float bj = b[j];
    float s = 0.0f, q = 0.0f;
    for (int r = blockIdx.x; r < n; r += gridDim.x) {
        float x = v[r * HID + j] + bj;
        s += x; q += x * x;
    }
    atomicAdd(&g_colsum[j], s);
    atomicAdd(&g_colsq[j], q);
}

// hnew = relu((v + b - mu)*rsqrt(var+eps)*g + bt) + hold
__global__ void bnapply_kernel(int v_sel, const float* __restrict__ b,
                               const float* __restrict__ g, const float* __restrict__ bt,
                               int hold_sel, int out_sel, int n) {
    const float* v = selbuf(v_sel);
    const float* hold = selbuf(hold_sel);
    float* out = selbuf(out_sel);
    int total = n * HID;
    float inv_n = 1.0f / (float)n;
    for (int idx = blockIdx.x * blockDim.x + threadIdx.x; idx < total;
         idx += gridDim.x * blockDim.x) {
        int j = idx & 127;
        float mu = g_colsum[j] * inv_n;
        float var = g_colsq[j] * inv_n - mu * mu;
        float x = (v[idx] + b[j] - mu) * rsqrtf(var + EPSBN) * g[j] + bt[j];
        out[idx] = fmaxf(x, 0.0f) + hold[idx];
    }
}

// ---------------- head: F = h3 @ Wf1 + bf1  (128 -> 32), warp per row ----------------
__global__ void gemm_f1_kernel(int a_sel, const float* __restrict__ W,
                               const float* __restrict__ b, int n) {
    __shared__ float Ws[HID * 32];  // 16 KB
    const float* A = selbuf(a_sel);
    for (int i = threadIdx.x; i < HID * 32; i += blockDim.x) Ws[i] = W[i];
    __syncthreads();
    int warp = (blockIdx.x * blockDim.x + threadIdx.x) >> 5;
    int lane = threadIdx.x & 31;
    int nwarps = (gridDim.x * blockDim.x) >> 5;
    float bl = b[lane];
    for (int row = warp; row < n; row += nwarps) {
        float4 hv = ((const float4*)A)[row * 32 + lane];  // lane holds k = 4*lane .. 4*lane+3
        float acc = 0.0f;
#pragma unroll
        for (int k = 0; k < HID; k++) {
            float comp = ((k & 3) == 0) ? hv.x : ((k & 3) == 1) ? hv.y
                       : ((k & 3) == 2) ? hv.z : hv.w;
            float hk = __shfl_sync(0xffffffffu, comp, k >> 2);
            acc += hk * Ws[k * 32 + lane];
        }
        g_f[row * 32 + lane] = acc + bl;
    }
}

__global__ void bnstats32_kernel(int n) {
    int j = threadIdx.x & 31;
    int sub = threadIdx.x >> 5;  // 4 sub-rows per block
    float s = 0.0f, q = 0.0f;
    for (int r = blockIdx.x * 4 + sub; r < n; r += gridDim.x * 4) {
        float x = g_f[r * 32 + j];
        s += x; q += x * x;
    }
    atomicAdd(&g_colsum[j], s);
    atomicAdd(&g_colsq[j], q);
}

__global__ void bnapply32_kernel(const float* __restrict__ g, const float* __restrict__ bt,
                                 int n) {
    int total = n * 32;
    float inv_n = 1.0f / (float)n;
    for (int idx = blockIdx.x * blockDim.x + threadIdx.x; idx < total;
         idx += gridDim.x * blockDim.x) {
        int j = idx & 31;
        float mu = g_colsum[j] * inv_n;
        float var = g_colsq[j] * inv_n - mu * mu;
        float x = (g_f[idx] - mu) * rsqrtf(var + EPSBN) * g[j] + bt[j];
        g_f[idx] = fmaxf(x, 0.0f);
    }
}

__global__ void final_kernel(const float* __restrict__ W2, const float* __restrict__ b2,
                             float* __restrict__ out, int n) {
    int i = blockIdx.x * blockDim.x + threadIdx.x;
    if (i >= n) return;
    const float* f = g_f + i * 32;
    float a0 = b2[0], a1 = b2[1];
#pragma unroll
    for (int k = 0; k < 32; k++) {
        float fv = f[k];
        a0 += fv * W2[2 * k];
        a1 += fv * W2[2 * k + 1];
    }
    out[2 * i] = tanhf(a0);
    out[2 * i + 1] = tanhf(a1);
}

// ---------------- launch ----------------
extern "C" void kernel_launch(void* const* d_in, const int* in_sizes, int n_in,
                              void* d_out, int out_size) {
    const float* x   = (const float*)d_in[0];
    const int*   ei  = (const int*)d_in[1];
    const float* We  = (const float*)d_in[2];
    const float* be  = (const float*)d_in[3];
    const float* W[3]  = {(const float*)d_in[4], (const float*)d_in[8],  (const float*)d_in[12]};
    const float* b[3]  = {(const float*)d_in[5], (const float*)d_in[9],  (const float*)d_in[13]};
    const float* g[3]  = {(const float*)d_in[6], (const float*)d_in[10], (const float*)d_in[14]};
    const float* bt[3] = {(const float*)d_in[7], (const float*)d_in[11], (const float*)d_in[15]};
    const float* Wf1 = (const float*)d_in[16];
    const float* bf1 = (const float*)d_in[17];
    const float* gf  = (const float*)d_in[18];
    const float* btf = (const float*)d_in[19];
    const float* Wf2 = (const float*)d_in[20];
    const float* bf2 = (const float*)d_in[21];
    float* out = (float*)d_out;

    int n = in_sizes[0] / 2;
    int e = in_sizes[1] / 2;

    // CSR build
    zero_cnt_kernel<<<(n + 255) / 256, 256>>>(n);
    count_kernel<<<(e + 255) / 256, 256>>>(ei, e);
    scan_kernel<<<1, 1024>>>(n);
    fill_kernel<<<(e + 255) / 256, 256>>>(ei, e);

    // encoder -> bufA (0)
    encoder_kernel<<<n, HID>>>(x, We, be, 0, n);

    // buffer rotation: (h, t, out) per layer: (A,C,C) (C,A,A) (A,C,C); agg always -> B
    int h_sel = 0;
    int t_sel = 2;
    for (int l = 0; l < 3; l++) {
        gemm128_kernel<<<(n + 31) / 32, 256>>>(h_sel, W[l], t_sel, n);
        agg_kernel<<<(n * 32 + 255) / 256, 256>>>(t_sel, 1, n);
        zero_stats_kernel<<<1, HID>>>();
        bnstats_kernel<<<256, HID>>>(1, b[l], n);
        bnapply_kernel<<<2048, 256>>>(1, b[l], g[l], bt[l], h_sel, t_sel, n);
        // new h is t_sel; old h buffer becomes the next t buffer
        int tmp = h_sel; h_sel = t_sel; t_sel = tmp;
    }

    // head
    gemm_f1_kernel<<<1184, 256>>>(h_sel, Wf1, bf1, n);
    zero_stats_kernel<<<1, HID>>>();
    bnstats32_kernel<<<256, HID>>>(n);
    bnapply32_kernel<<<2048, 256>>>(gf, btf, n);
    final_kernel<<<(n + 255) / 256, 256>>>(Wf2, bf2, out, n);
}

// round 5
// speedup vs baseline: 1.7492x; 1.7492x over previous
#include <cuda_runtime.h>
#include <math.h>

#define N_MAX 100000
#define E_MAX 1600000
#define HID 128
#define EPSBN 1e-5f

// ---------------- scratch (device globals; no allocation) ----------------
__device__ float g_bufA[N_MAX * HID];
__device__ float g_bufB[N_MAX * HID];
__device__ float g_dinv[N_MAX];
__device__ int   g_cnt[N_MAX];
__device__ int   g_rowptr[N_MAX + 1];
__device__ int   g_rank[E_MAX];
__device__ int   g_csr_src[E_MAX];
__device__ float g_csr_ws[E_MAX];     // dinv[src] per edge
__device__ float g_colsum[512];       // 4 slices of 128 (layers 0..2, head)
__device__ float g_colsq[512];
__device__ float g_f[N_MAX * 32];

__device__ __forceinline__ float* selbuf(int s) { return s ? g_bufB : g_bufA; }

// ---------------- init: zero counts + all BN stat slices ----------------
__global__ void init_kernel(int n) {
    int i = blockIdx.x * blockDim.x + threadIdx.x;
    if (i < n) g_cnt[i] = 0;
    if (i < 512) { g_colsum[i] = 0.0f; g_colsq[i] = 0.0f; }
}

// ---------------- count + per-edge rank ----------------
__global__ void count_rank_kernel(const int* __restrict__ ei, int e) {
    int i = blockIdx.x * blockDim.x + threadIdx.x;
    if (i < e) {
        int dst = ei[e + i];
        g_rank[i] = atomicAdd(&g_cnt[dst], 1);
    }
}

// ---------------- exclusive scan (1024 threads, shfl-based) + dinv ----------------
__global__ void scan_kernel(int n) {
    __shared__ int wsum[32];
    int tid = threadIdx.x;
    int lane = tid & 31, wid = tid >> 5;
    int chunk = (n + 1023) >> 10;
    int start = tid * chunk;
    int end = start + chunk; if (end > n) end = n;
    int s = 0;
    for (int i = start; i < end; i++) s += g_cnt[i];

    unsigned full = 0xffffffffu;
    int v = s;
#pragma unroll
    for (int o = 1; o < 32; o <<= 1) {
        int t = __shfl_up_sync(full, v, o);
        if (lane >= o) v += t;
    }
    if (lane == 31) wsum[wid] = v;
    __syncthreads();
    if (wid == 0) {
        int w = wsum[lane];
#pragma unroll
        for (int o = 1; o < 32; o <<= 1) {
            int t = __shfl_up_sync(full, w, o);
            if (lane >= o) w += t;
        }
        wsum[lane] = w;
    }
    __syncthreads();
    int base = (wid > 0) ? wsum[wid - 1] : 0;
    int acc = base + v - s;   // exclusive prefix for this thread's chunk
    for (int i = start; i < end; i++) {
        g_rowptr[i] = acc;
        int c = g_cnt[i];
        acc += c;
        g_dinv[i] = rsqrtf((float)c + 1.0f);   // +1 self-loop
    }
    if (tid == 1023) g_rowptr[n] = base + v - s + (end > start ? (acc - (base + v - s)) : 0);
}

// ---------------- fill (atomic-free via rank) ----------------
__global__ void fill_kernel(const int* __restrict__ ei, int e) {
    int i = blockIdx.x * blockDim.x + threadIdx.x;
    if (i < e) {
        int src = ei[i];
        int dst = ei[e + i];
        int idx = g_rowptr[dst] + g_rank[i];
        g_csr_src[idx] = src;
        g_csr_ws[idx] = g_dinv[src];
    }
}

// ---------------- encoder: h = relu(x @ We + be), x[N,2] ----------------
__global__ void encoder_kernel(const float* __restrict__ x, const float* __restrict__ We,
                               const float* __restrict__ be, int out_sel, int n) {
    int i = blockIdx.x;
    int j = threadIdx.x;
    if (i >= n) return;
    float v = x[2 * i] * We[j] + x[2 * i + 1] * We[HID + j] + be[j];
    selbuf(out_sel)[i * HID + j] = fmaxf(v, 0.0f);
}

// ---------------- fused: C = Agg(h) @ W, plus BN column stats (no bias: BN absorbs it) ----
// block 256, tile 64 rows x 128 cols, micro 8x4. smem = 32KB As + 16KB Bs = 48KB.
__global__ __launch_bounds__(256, 3)
void agg_gemm_kernel(int h_sel, const float* __restrict__ W, int c_sel, int layer, int n) {
    __shared__ float As[64][HID];
    __shared__ float Bs[32][HID];
    const float4* t4 = (const float4*)selbuf(h_sel);
    float* C = selbuf(c_sel);
    int tid = threadIdx.x;
    int lane = tid & 31, warp = tid >> 5;
    int row0 = blockIdx.x * 64;

    // ---- phase A: aggregate 64 rows into As (warp per node, 8 nodes per warp) ----
#pragma unroll
    for (int r8 = 0; r8 < 8; r8++) {
        int r = warp * 8 + r8;
        int node = row0 + r;
        float4 acc = make_float4(0.f, 0.f, 0.f, 0.f);
        if (node < n) {
            float di = g_dinv[node];
            float4 v = t4[node * 32 + lane];
            acc.x = di * v.x; acc.y = di * v.y; acc.z = di * v.z; acc.w = di * v.w;
            int e = g_rowptr[node];
            int end = g_rowptr[node + 1];
            for (; e + 4 <= end; e += 4) {
                int s0 = g_csr_src[e], s1 = g_csr_src[e + 1];
                int s2 = g_csr_src[e + 2], s3 = g_csr_src[e + 3];
                float w0 = g_csr_ws[e], w1 = g_csr_ws[e + 1];
                float w2 = g_csr_ws[e + 2], w3 = g_csr_ws[e + 3];
                float4 u0 = t4[s0 * 32 + lane];
                float4 u1 = t4[s1 * 32 + lane];
                float4 u2 = t4[s2 * 32 + lane];
                float4 u3 = t4[s3 * 32 + lane];
                acc.x += w0 * u0.x + w1 * u1.x + w2 * u2.x + w3 * u3.x;
                acc.y += w0 * u0.y + w1 * u1.y + w2 * u2.y + w3 * u3.y;
                acc.z += w0 * u0.z + w1 * u1.z + w2 * u2.z + w3 * u3.z;
                acc.w += w0 * u0.w + w1 * u1.w + w2 * u2.w + w3 * u3.w;
            }
            for (; e < end; e++) {
                int s = g_csr_src[e];
                float w = g_csr_ws[e];
                float4 u = t4[s * 32 + lane];
                acc.x += w * u.x; acc.y += w * u.y; acc.z += w * u.z; acc.w += w * u.w;
            }
            acc.x *= di; acc.y *= di; acc.z *= di; acc.w *= di;
        }
        *(float4*)&As[r][lane * 4] = acc;
    }

    // ---- phase B: GEMM, k in 4 chunks of 32 ----
    int tx = lane, ty = warp;
    float acc2[8][4];
#pragma unroll
    for (int i = 0; i < 8; i++)
#pragma unroll
        for (int j = 0; j < 4; j++) acc2[i][j] = 0.0f;

    for (int kc = 0; kc < 4; kc++) {
        __syncthreads();
        {
            const float4* Wv = (const float4*)(W + kc * 32 * HID);
            float4* Bv = (float4*)Bs;
            for (int i = tid; i < 32 * 32; i += 256) Bv[i] = Wv[i];
        }
        __syncthreads();
#pragma unroll
        for (int k = 0; k < 32; k++) {
            float4 b = *(const float4*)&Bs[k][tx * 4];
#pragma unroll
            for (int i = 0; i < 8; i++) {
                float a = As[ty * 8 + i][kc * 32 + k];
                acc2[i][0] += a * b.x;
                acc2[i][1] += a * b.y;
                acc2[i][2] += a * b.z;
                acc2[i][3] += a * b.w;
            }
        }
    }

    // ---- epilogue: write C + BN stats (rows >= n contribute exact zeros) ----
    float ps[4] = {0.f, 0.f, 0.f, 0.f};
    float pq[4] = {0.f, 0.f, 0.f, 0.f};
#pragma unroll
    for (int i = 0; i < 8; i++) {
        int row = row0 + ty * 8 + i;
        if (row < n) {
            *(float4*)&C[row * HID + tx * 4] =
                make_float4(acc2[i][0], acc2[i][1], acc2[i][2], acc2[i][3]);
        }
#pragma unroll
        for (int j = 0; j < 4; j++) {
            ps[j] += acc2[i][j];
            pq[j] += acc2[i][j] * acc2[i][j];
        }
    }
    __syncthreads();                // done with Bs; reuse as 256-float reducer
    float* sc = (float*)Bs;
    sc[tid] = 0.0f;                 // 256 threads zero 256 slots
    __syncthreads();
#pragma unroll
    for (int j = 0; j < 4; j++) {
        atomicAdd(&sc[tx * 4 + j], ps[j]);
        atomicAdd(&sc[128 + tx * 4 + j], pq[j]);
    }
    __syncthreads();
    if (tid < 128) {
        atomicAdd(&g_colsum[layer * 128 + tid], sc[tid]);
        atomicAdd(&g_colsq[layer * 128 + tid], sc[128 + tid]);
    }
}

// ---------------- bnapply: c = relu(bn(c)) + h  (in place into c) ----------------
__global__ void bnapply_kernel(int c_sel, int h_sel, const float* __restrict__ g,
                               const float* __restrict__ bt, int layer, int n) {
    __shared__ float sscale[HID], sshift[HID];
    int tid = threadIdx.x;
    if (tid < HID) {
        float inv_n = 1.0f / (float)n;
        float mu = g_colsum[layer * 128 + tid] * inv_n;
        float var = g_colsq[layer * 128 + tid] * inv_n - mu * mu;
        float sc = rsqrtf(var + EPSBN) * g[tid];
        sscale[tid] = sc;
        sshift[tid] = bt[tid] - mu * sc;
    }
    __syncthreads();
    float4* c4 = (float4*)selbuf(c_sel);
    const float4* h4 = (const float4*)selbuf(h_sel);
    int total = n * 32;
    for (int idx = blockIdx.x * blockDim.x + tid; idx < total; idx += gridDim.x * blockDim.x) {
        int j4 = (idx & 31) * 4;
        float4 c = c4[idx];
        float4 h = h4[idx];
        c.x = fmaxf(c.x * sscale[j4]     + sshift[j4],     0.f) + h.x;
        c.y = fmaxf(c.y * sscale[j4 + 1] + sshift[j4 + 1], 0.f) + h.y;
        c.z = fmaxf(c.z * sscale[j4 + 2] + sshift[j4 + 2], 0.f) + h.z;
        c.w = fmaxf(c.w * sscale[j4 + 3] + sshift[j4 + 3], 0.f) + h.w;
        c4[idx] = c;
    }
}

// ---------------- head: h3 = relu(bn3(C3)) + h2 computed on the fly; f = h3 @ Wf1 ----
// (bf1 absorbed by head BN). Also accumulates head-BN stats.
__global__ __launch_bounds__(256)
void head_kernel(int v_sel, int hold_sel, const float* __restrict__ g3,
                 const float* __restrict__ bt3, const float* __restrict__ Wf1, int n) {
    __shared__ float Ws[HID * 32];
    __shared__ float sscale[HID], sshift[HID];
    __shared__ float sstat[64];
    int tid = threadIdx.x, lane = tid & 31;
    for (int i = tid; i < HID * 32; i += 256) Ws[i] = Wf1[i];
    if (tid < HID) {
        float inv_n = 1.0f / (float)n;
        float mu = g_colsum[256 + tid] * inv_n;
        float var = g_colsq[256 + tid] * inv_n - mu * mu;
        float sc = rsqrtf(var + EPSBN) * g3[tid];
        sscale[tid] = sc;
        sshift[tid] = bt3[tid] - mu * sc;
    }
    if (tid < 64) sstat[tid] = 0.0f;
    __syncthreads();

    const float4* v4 = (const float4*)selbuf(v_sel);
    const float4* h4 = (const float4*)selbuf(hold_sel);
    float s0 = sscale[lane * 4], s1 = sscale[lane * 4 + 1];
    float s2 = sscale[lane * 4 + 2], s3 = sscale[lane * 4 + 3];
    float t0 = sshift[lane * 4], t1 = sshift[lane * 4 + 1];
    float t2 = sshift[lane * 4 + 2], t3 = sshift[lane * 4 + 3];

    int warp_g = (blockIdx.x * 256 + tid) >> 5;
    int nw = (gridDim.x * 256) >> 5;
    float fs = 0.f, fq = 0.f;
    for (int row = warp_g; row < n; row += nw) {
        float4 c = v4[row * 32 + lane];
        float4 h = h4[row * 32 + lane];
        float x0 = fmaxf(c.x * s0 + t0, 0.f) + h.x;
        float x1 = fmaxf(c.y * s1 + t1, 0.f) + h.y;
        float x2 = fmaxf(c.z * s2 + t2, 0.f) + h.z;
        float x3 = fmaxf(c.w * s3 + t3, 0.f) + h.w;
        float acc = 0.0f;
#pragma unroll
        for (int k = 0; k < HID; k++) {
            float comp = ((k & 3) == 0) ? x0 : ((k & 3) == 1) ? x1
                       : ((k & 3) == 2) ? x2 : x3;
            float hk = __shfl_sync(0xffffffffu, comp, k >> 2);
            acc += hk * Ws[k * 32 + lane];
        }
        g_f[row * 32 + lane] = acc;
        fs += acc; fq += acc * acc;
    }
    atomicAdd(&sstat[lane], fs);
    atomicAdd(&sstat[32 + lane], fq);
    __syncthreads();
    if (tid < 32) {
        atomicAdd(&g_colsum[384 + tid], sstat[tid]);
        atomicAdd(&g_colsq[384 + tid], sstat[32 + tid]);
    }
}

// ---------------- final: out = tanh(relu(bn(f)) @ Wf2 + bf2) ----------------
__global__ void final_kernel(const float* __restrict__ gf, const float* __restrict__ btf,
                             const float* __restrict__ Wf2, const float* __restrict__ bf2,
                             float* __restrict__ out, int n) {
    __shared__ float sscale[32], sshift[32], sW[64], sb[2];
    int tid = threadIdx.x;
    if (tid < 32) {
        float inv_n = 1.0f / (float)n;
        float mu = g_colsum[384 + tid] * inv_n;
        float var = g_colsq[384 + tid] * inv_n - mu * mu;
        float sc = rsqrtf(var + EPSBN) * gf[tid];
        sscale[tid] = sc;
        sshift[tid] = btf[tid] - mu * sc;
    }
    if (tid < 64) sW[tid] = Wf2[tid];
    if (tid < 2) sb[tid] = bf2[tid];
    __syncthreads();
    int i = blockIdx.x * blockDim.x + tid;
    if (i >= n) return;
    const float* f = g_f + i * 32;
    float a0 = sb[0], a1 = sb[1];
#pragma unroll
    for (int k = 0; k < 32; k++) {
        float x = fmaxf(f[k] * sscale[k] + sshift[k], 0.f);
        a0 += x * sW[2 * k];
        a1 += x * sW[2 * k + 1];
    }
    out[2 * i] = tanhf(a0);
    out[2 * i + 1] = tanhf(a1);
}

// ---------------- launch ----------------
extern "C" void kernel_launch(void* const* d_in, const int* in_sizes, int n_in,
                              void* d_out, int out_size) {
    const float* x   = (const float*)d_in[0];
    const int*   ei  = (const int*)d_in[1];
    const float* We  = (const float*)d_in[2];
    const float* be  = (const float*)d_in[3];
    const float* W[3]  = {(const float*)d_in[4], (const float*)d_in[8],  (const float*)d_in[12]};
    const float* g[3]  = {(const float*)d_in[6], (const float*)d_in[10], (const float*)d_in[14]};
    const float* bt[3] = {(const float*)d_in[7], (const float*)d_in[11], (const float*)d_in[15]};
    const float* Wf1 = (const float*)d_in[16];
    const float* gf  = (const float*)d_in[18];
    const float* btf = (const float*)d_in[19];
    const float* Wf2 = (const float*)d_in[20];
    const float* bf2 = (const float*)d_in[21];
    float* out = (float*)d_out;

    int n = in_sizes[0] / 2;
    int e = in_sizes[1] / 2;

    // CSR build (rank-based, atomic-free fill)
    init_kernel<<<(n + 255) / 256, 256>>>(n);
    count_rank_kernel<<<(e + 255) / 256, 256>>>(ei, e);
    scan_kernel<<<1, 1024>>>(n);
    fill_kernel<<<(e + 255) / 256, 256>>>(ei, e);

    // encoder -> bufA
    encoder_kernel<<<n, HID>>>(x, We, be, 0, n);

    // layers: h/c ping-pong between bufA(0) / bufB(1)
    int h_sel = 0, c_sel = 1;
    for (int l = 0; l < 3; l++) {
        agg_gemm_kernel<<<(n + 63) / 64, 256>>>(h_sel, W[l], c_sel, l, n);
        if (l < 2) {
            bnapply_kernel<<<2048, 256>>>(c_sel, h_sel, g[l], bt[l], l, n);
            int t = h_sel; h_sel = c_sel; c_sel = t;
        }
    }
    // after loop: c_sel holds raw C3 (pre-BN), h_sel holds h2

    head_kernel<<<1536, 256>>>(c_sel, h_sel, g[2], bt[2], Wf1, n);
    final_kernel<<<(n + 255) / 256, 256>>>(gf, btf, Wf2, bf2, out, n);
}